// round 3
// baseline (speedup 1.0000x reference)
#include <cuda_runtime.h>
#include <cuda_bf16.h>

// Problem constants
#define BB   8
#define NN   1024
#define CC   512
#define HH   4
#define HD   128
#define BN_TOK (BB * NN)          // 8192
#define C3  (3 * CC)              // 1536
#define SCALE 0.08838834764831845f  // 128^-0.5

// Scratch (device globals: no allocation allowed)
__device__ float g_qkv[(size_t)BN_TOK * C3];          // [B*N, 3C]  50.3 MB
__device__ float g_s[(size_t)BB * HH * NN * NN];      // [B,H,N,N]  134 MB (reused in-place for P)
__device__ float g_o[(size_t)BN_TOK * CC];            // [B,N,C]    16.8 MB

// ---------------------------------------------------------------------------
// Generic tiled SGEMM: C = alpha * A (.) op(B) (+ bias)
//   A: [M,K] row-major, lda
//   TRANSB=true : B is [N,K] row-major (C = A B^T), ldb = row stride
//   TRANSB=false: B is [K,N] row-major (C = A B),   ldb = row stride
// Two-level batch offset: z -> (zi = z % bin, zo = z / bin)
// BM=BN=128, BK=16, 256 threads, 8x8 per-thread micro-tile.
// All dims assumed multiples of tile sizes (true for this problem).
// ---------------------------------------------------------------------------
template<bool TRANSB, bool BIAS>
__global__ __launch_bounds__(256) void sgemm_kernel(
    const float* __restrict__ A, const float* __restrict__ B,
    float* __restrict__ C, const float* __restrict__ bias,
    int M, int Nc, int K, int lda, int ldb, int ldc,
    int bin,
    long long sAi, long long sAo,
    long long sBi, long long sBo,
    long long sCi, long long sCo,
    float alpha)
{
    int z  = blockIdx.z;
    int zi = z % bin, zo = z / bin;
    A += (size_t)zi * sAi + (size_t)zo * sAo;
    B += (size_t)zi * sBi + (size_t)zo * sBo;
    C += (size_t)zi * sCi + (size_t)zo * sCo;

    __shared__ float As[16][128];
    __shared__ float Bs[16][128];

    const int tid = threadIdx.x;
    const int tx  = tid & 15;        // 0..15 -> N micro
    const int ty  = tid >> 4;        // 0..15 -> M micro
    const int rowBase = blockIdx.y * 128;
    const int colBase = blockIdx.x * 128;

    float acc[8][8];
    #pragma unroll
    for (int i = 0; i < 8; i++)
        #pragma unroll
        for (int j = 0; j < 8; j++) acc[i][j] = 0.0f;

    for (int kt = 0; kt < K; kt += 16) {
        // A tile: 128 rows x 16 k, transposed store into As[k][m]
        #pragma unroll
        for (int r = 0; r < 2; r++) {
            int idx = r * 256 + tid;
            int row = idx >> 2;
            int kq  = (idx & 3) << 2;
            float4 va = *(const float4*)(A + (size_t)(rowBase + row) * lda + kt + kq);
            As[kq + 0][row] = va.x; As[kq + 1][row] = va.y;
            As[kq + 2][row] = va.z; As[kq + 3][row] = va.w;
        }
        if (TRANSB) {
            // B tile: 128 n-rows x 16 k, transposed store into Bs[k][n]
            #pragma unroll
            for (int r = 0; r < 2; r++) {
                int idx = r * 256 + tid;
                int row = idx >> 2;
                int kq  = (idx & 3) << 2;
                float4 vb = *(const float4*)(B + (size_t)(colBase + row) * ldb + kt + kq);
                Bs[kq + 0][row] = vb.x; Bs[kq + 1][row] = vb.y;
                Bs[kq + 2][row] = vb.z; Bs[kq + 3][row] = vb.w;
            }
        } else {
            // B tile: 16 k-rows x 128 n, direct store Bs[k][n]
            #pragma unroll
            for (int r = 0; r < 2; r++) {
                int idx  = r * 256 + tid;
                int krow = idx >> 5;
                int nq   = (idx & 31) << 2;
                *(float4*)&Bs[krow][nq] =
                    *(const float4*)(B + (size_t)(kt + krow) * ldb + colBase + nq);
            }
        }
        __syncthreads();

        #pragma unroll
        for (int k = 0; k < 16; k++) {
            float ra[8], rb[8];
            #pragma unroll
            for (int i = 0; i < 8; i++) ra[i] = As[k][ty * 8 + i];
            #pragma unroll
            for (int j = 0; j < 8; j++) rb[j] = Bs[k][tx * 8 + j];
            #pragma unroll
            for (int i = 0; i < 8; i++)
                #pragma unroll
                for (int j = 0; j < 8; j++)
                    acc[i][j] = fmaf(ra[i], rb[j], acc[i][j]);
        }
        __syncthreads();
    }

    // Epilogue
    #pragma unroll
    for (int i = 0; i < 8; i++) {
        int m = rowBase + ty * 8 + i;
        float* crow = C + (size_t)m * ldc + colBase + tx * 8;
        #pragma unroll
        for (int j = 0; j < 8; j += 4) {
            float4 o;
            o.x = alpha * acc[i][j + 0];
            o.y = alpha * acc[i][j + 1];
            o.z = alpha * acc[i][j + 2];
            o.w = alpha * acc[i][j + 3];
            if (BIAS) {
                int nb = colBase + tx * 8 + j;
                o.x += bias[nb]; o.y += bias[nb + 1];
                o.z += bias[nb + 2]; o.w += bias[nb + 3];
            }
            *(float4*)(crow + j) = o;
        }
    }
}

// ---------------------------------------------------------------------------
// Cross-head mix + softmax, in-place over g_s.
// One CTA per (b, n): loads S[b, h, n, :] for all 4 heads into smem,
// for each output head i: row_i = sum_h M[i,h]*S_h, softmax, write P[b,i,n,:].
// ---------------------------------------------------------------------------
__global__ __launch_bounds__(256) void mix_softmax_kernel(
    float* __restrict__ S,
    const float* __restrict__ w_main,
    const float* __restrict__ w_rest)
{
    __shared__ float s[HH][NN];   // 16 KB
    __shared__ float Mm[HH * HH];
    __shared__ float red[8];

    const int b   = blockIdx.x / NN;
    const int n   = blockIdx.x % NN;
    const int tid = threadIdx.x;

    if (tid < HH * HH) {
        int i = tid / HH, j = tid % HH;
        Mm[tid] = (i == j) ? w_main[i]
                           : w_rest[i * (HH - 1) + (j < i ? j : j - 1)];
    }

    #pragma unroll
    for (int h = 0; h < HH; h++) {
        const float* src = S + ((size_t)(b * HH + h) * NN + n) * NN;
        for (int m = tid; m < NN; m += 256) s[h][m] = src[m];
    }
    __syncthreads();

    #pragma unroll
    for (int i = 0; i < HH; i++) {
        float v[4];
        float mx = -3.4e38f;
        #pragma unroll
        for (int j = 0; j < 4; j++) {
            int m = tid + j * 256;
            v[j] = Mm[i * HH + 0] * s[0][m] + Mm[i * HH + 1] * s[1][m]
                 + Mm[i * HH + 2] * s[2][m] + Mm[i * HH + 3] * s[3][m];
            mx = fmaxf(mx, v[j]);
        }
        // block max
        #pragma unroll
        for (int o = 16; o > 0; o >>= 1) mx = fmaxf(mx, __shfl_xor_sync(0xffffffffu, mx, o));
        if ((tid & 31) == 0) red[tid >> 5] = mx;
        __syncthreads();
        float rmax = red[0];
        #pragma unroll
        for (int w = 1; w < 8; w++) rmax = fmaxf(rmax, red[w]);
        __syncthreads();

        float sum = 0.0f;
        #pragma unroll
        for (int j = 0; j < 4; j++) { v[j] = expf(v[j] - rmax); sum += v[j]; }
        #pragma unroll
        for (int o = 16; o > 0; o >>= 1) sum += __shfl_xor_sync(0xffffffffu, sum, o);
        if ((tid & 31) == 0) red[tid >> 5] = sum;
        __syncthreads();
        float rsum = red[0];
        #pragma unroll
        for (int w = 1; w < 8; w++) rsum += red[w];
        __syncthreads();

        float inv = 1.0f / rsum;
        float* dst = S + ((size_t)(b * HH + i) * NN + n) * NN;
        #pragma unroll
        for (int j = 0; j < 4; j++) dst[tid + j * 256] = v[j] * inv;
    }
}

// ---------------------------------------------------------------------------
extern "C" void kernel_launch(void* const* d_in, const int* in_sizes, int n_in,
                              void* d_out, int out_size)
{
    const float* x      = (const float*)d_in[0];  // [B,N,C]
    const float* w_qkv  = (const float*)d_in[1];  // [3C,C]
    const float* w_proj = (const float*)d_in[2];  // [C,C]
    const float* b_proj = (const float*)d_in[3];  // [C]
    const float* w_main = (const float*)d_in[4];  // [H]
    const float* w_rest = (const float*)d_in[5];  // [H,H-1]
    float* out = (float*)d_out;                   // [B,N,C]

    float* qkv; cudaGetSymbolAddress((void**)&qkv, g_qkv);
    float* S;   cudaGetSymbolAddress((void**)&S,   g_s);
    float* O;   cudaGetSymbolAddress((void**)&O,   g_o);

    // 1) QKV = X @ Wqkv^T : [8192,1536,512]
    sgemm_kernel<true, false><<<dim3(C3 / 128, BN_TOK / 128, 1), 256>>>(
        x, w_qkv, qkv, nullptr,
        BN_TOK, C3, CC, CC, CC, C3,
        1, 0, 0, 0, 0, 0, 0, 1.0f);

    // 2) S[b,h] = scale * Q_bh @ K_bh^T : 32 x [1024,1024,128]
    //    Q rows live at qkv + b*N*3C + h*HD, K at +C, row stride 3C
    sgemm_kernel<true, false><<<dim3(NN / 128, NN / 128, BB * HH), 256>>>(
        qkv, qkv + CC, S, nullptr,
        NN, NN, HD, C3, C3, NN,
        HH,
        /*sAi*/ HD, /*sAo*/ (long long)NN * C3,
        /*sBi*/ HD, /*sBo*/ (long long)NN * C3,
        /*sCi*/ (long long)NN * NN, /*sCo*/ (long long)HH * NN * NN,
        SCALE);

    // 3) cross-head mix + softmax (in-place over S)
    mix_softmax_kernel<<<BB * NN, 256>>>(S, w_main, w_rest);

    // 4) O[b,h] = P_bh @ V_bh : 32 x [1024,128,1024], V at qkv + 2C, row stride 3C
    sgemm_kernel<false, false><<<dim3(HD / 128, NN / 128, BB * HH), 256>>>(
        S, qkv + 2 * CC, O, nullptr,
        NN, HD, NN, NN, C3, CC,
        HH,
        /*sAi*/ (long long)NN * NN, /*sAo*/ (long long)HH * NN * NN,
        /*sBi*/ HD, /*sBo*/ (long long)NN * C3,
        /*sCi*/ HD, /*sCo*/ (long long)NN * CC,
        1.0f);

    // 5) out = O @ Wproj^T + b : [8192,512,512]
    sgemm_kernel<true, true><<<dim3(CC / 128, BN_TOK / 128, 1), 256>>>(
        O, w_proj, out, b_proj,
        BN_TOK, CC, CC, CC, CC, CC,
        1, 0, 0, 0, 0, 0, 0, 1.0f);
}

// round 5
// speedup vs baseline: 1.7754x; 1.7754x over previous
#include <cuda_runtime.h>
#include <cuda_bf16.h>
#include <cstdint>

// Problem constants
#define BB   8
#define NN   1024
#define CC   512
#define HH   4
#define HD   128
#define BN_TOK (BB * NN)          // 8192
#define C3  (3 * CC)              // 1536
#define SCALE 0.08838834764831845f  // 128^-0.5

// Scratch (device globals: no allocation allowed)
__device__ float g_qkv[(size_t)BN_TOK * C3];          // [B*N, 3C]  50.3 MB
__device__ float g_s[(size_t)BB * HH * NN * NN];      // [B,H,N,N]  134 MB (reused in-place for P)
__device__ float g_o[(size_t)BN_TOK * CC];            // [B,N,C]    16.8 MB

__device__ __forceinline__ unsigned f2tf32(float x) {
    unsigned r;
    asm("cvt.rna.tf32.f32 %0, %1;" : "=r"(r) : "f"(x));
    return r;
}

__device__ __forceinline__ void mma_tf32(float* c, const unsigned* a, const unsigned* b) {
    asm volatile(
        "mma.sync.aligned.m16n8k8.row.col.f32.tf32.tf32.f32 "
        "{%0,%1,%2,%3}, {%4,%5,%6,%7}, {%8,%9}, {%0,%1,%2,%3};"
        : "+f"(c[0]), "+f"(c[1]), "+f"(c[2]), "+f"(c[3])
        : "r"(a[0]), "r"(a[1]), "r"(a[2]), "r"(a[3]), "r"(b[0]), "r"(b[1]));
}

// ---------------------------------------------------------------------------
// tf32 tensor-core GEMM: C = alpha * A (.) op(B) (+ bias)
//   A: [M,K] row-major, lda
//   TRANSB=true : B is [N,K] row-major (C = A B^T)
//   TRANSB=false: B is [K,N] row-major (C = A B)
// CTA tile 128x128, BK=32, 256 threads = 8 warps, warp tile 32x64
// (2 x 8 of m16n8k8 tf32 mma). fp32 accumulation.
// All dims multiples of tile sizes (true for this problem).
// ---------------------------------------------------------------------------
template<bool TRANSB, bool BIAS>
__global__ __launch_bounds__(256) void tgemm_kernel(
    const float* __restrict__ A, const float* __restrict__ B,
    float* __restrict__ C, const float* __restrict__ bias,
    int K, int lda, int ldb, int ldc,
    int bin,
    long long sAi, long long sAo,
    long long sBi, long long sBo,
    long long sCi, long long sCo,
    float alpha)
{
    int z  = blockIdx.z;
    int zi = z % bin, zo = z / bin;
    A += (size_t)zi * sAi + (size_t)zo * sAo;
    B += (size_t)zi * sBi + (size_t)zo * sBo;
    C += (size_t)zi * sCi + (size_t)zo * sCo;

    __shared__ unsigned As[32][136];   // [k][m], pad 8 -> conflict-free frag loads
    __shared__ unsigned Bs[32][136];   // [k][n]

    const int tid  = threadIdx.x;
    const int lane = tid & 31;
    const int g    = lane >> 2;        // groupID 0..7
    const int tg   = lane & 3;         // thread-in-group 0..3
    const int wm   = (tid >> 5) & 3;   // warp m-index 0..3  (32 rows each)
    const int wn   = tid >> 7;         // warp n-index 0..1  (64 cols each)
    const int mbase = wm * 32;
    const int nbase = wn * 64;

    const int rowBase = blockIdx.y * 128;
    const int colBase = blockIdx.x * 128;

    float acc[2][8][4];
    #pragma unroll
    for (int mi = 0; mi < 2; mi++)
        #pragma unroll
        for (int ni = 0; ni < 8; ni++)
            #pragma unroll
            for (int r = 0; r < 4; r++) acc[mi][ni][r] = 0.0f;

    for (int kt = 0; kt < K; kt += 32) {
        // ---- A tile: 128 rows x 32 k, store transposed As[k][m] as tf32 bits
        #pragma unroll
        for (int r = 0; r < 4; r++) {
            int idx = r * 256 + tid;
            int row = idx >> 3;              // 0..127
            int kq  = (idx & 7) << 2;        // 0,4,...,28
            float4 v = *(const float4*)(A + (size_t)(rowBase + row) * lda + kt + kq);
            As[kq + 0][row] = f2tf32(v.x);
            As[kq + 1][row] = f2tf32(v.y);
            As[kq + 2][row] = f2tf32(v.z);
            As[kq + 3][row] = f2tf32(v.w);
        }
        if (TRANSB) {
            // B tile: 128 n-rows x 32 k, store transposed Bs[k][n]
            #pragma unroll
            for (int r = 0; r < 4; r++) {
                int idx = r * 256 + tid;
                int row = idx >> 3;
                int kq  = (idx & 7) << 2;
                float4 v = *(const float4*)(B + (size_t)(colBase + row) * ldb + kt + kq);
                Bs[kq + 0][row] = f2tf32(v.x);
                Bs[kq + 1][row] = f2tf32(v.y);
                Bs[kq + 2][row] = f2tf32(v.z);
                Bs[kq + 3][row] = f2tf32(v.w);
            }
        } else {
            // B tile: 32 k-rows x 128 n, direct Bs[k][n]
            #pragma unroll
            for (int r = 0; r < 4; r++) {
                int idx  = r * 256 + tid;
                int krow = idx >> 5;         // 0..31
                int nq   = (idx & 31) << 2;  // 0..124
                float4 v = *(const float4*)(B + (size_t)(kt + krow) * ldb + colBase + nq);
                uint4 u;
                u.x = f2tf32(v.x); u.y = f2tf32(v.y);
                u.z = f2tf32(v.z); u.w = f2tf32(v.w);
                *(uint4*)&Bs[krow][nq] = u;
            }
        }
        __syncthreads();

        #pragma unroll
        for (int ks = 0; ks < 32; ks += 8) {
            unsigned a[2][4], b[8][2];
            #pragma unroll
            for (int mi = 0; mi < 2; mi++) {
                int m = mbase + mi * 16 + g;
                a[mi][0] = As[ks + tg    ][m];
                a[mi][1] = As[ks + tg    ][m + 8];
                a[mi][2] = As[ks + tg + 4][m];
                a[mi][3] = As[ks + tg + 4][m + 8];
            }
            #pragma unroll
            for (int ni = 0; ni < 8; ni++) {
                int n = nbase + ni * 8 + g;
                b[ni][0] = Bs[ks + tg    ][n];
                b[ni][1] = Bs[ks + tg + 4][n];
            }
            #pragma unroll
            for (int mi = 0; mi < 2; mi++)
                #pragma unroll
                for (int ni = 0; ni < 8; ni++)
                    mma_tf32(acc[mi][ni], a[mi], b[ni]);
        }
        __syncthreads();
    }

    // ---- Epilogue ----
    #pragma unroll
    for (int mi = 0; mi < 2; mi++) {
        #pragma unroll
        for (int ni = 0; ni < 8; ni++) {
            int row = rowBase + mbase + mi * 16 + g;
            int col = colBase + nbase + ni * 8 + tg * 2;
            float bx = 0.f, by = 0.f;
            if (BIAS) { bx = bias[col]; by = bias[col + 1]; }
            float2 v0, v1;
            v0.x = alpha * acc[mi][ni][0] + bx;
            v0.y = alpha * acc[mi][ni][1] + by;
            v1.x = alpha * acc[mi][ni][2] + bx;
            v1.y = alpha * acc[mi][ni][3] + by;
            *(float2*)(C + (size_t)row * ldc + col)       = v0;
            *(float2*)(C + (size_t)(row + 8) * ldc + col) = v1;
        }
    }
}

// ---------------------------------------------------------------------------
// Cross-head mix + softmax, in-place over g_s.
// One CTA per (b, n): loads S[b, h, n, :] for all 4 heads into smem,
// for each output head i: row_i = sum_h M[i,h]*S_h, softmax, write P[b,i,n,:].
// ---------------------------------------------------------------------------
__global__ __launch_bounds__(256) void mix_softmax_kernel(
    float* __restrict__ S,
    const float* __restrict__ w_main,
    const float* __restrict__ w_rest)
{
    __shared__ float s[HH][NN];   // 16 KB
    __shared__ float Mm[HH * HH];
    __shared__ float red[8];

    const int b   = blockIdx.x / NN;
    const int n   = blockIdx.x % NN;
    const int tid = threadIdx.x;

    if (tid < HH * HH) {
        int i = tid / HH, j = tid % HH;
        Mm[tid] = (i == j) ? w_main[i]
                           : w_rest[i * (HH - 1) + (j < i ? j : j - 1)];
    }

    #pragma unroll
    for (int h = 0; h < HH; h++) {
        const float* src = S + ((size_t)(b * HH + h) * NN + n) * NN;
        for (int m = tid; m < NN; m += 256) s[h][m] = src[m];
    }
    __syncthreads();

    #pragma unroll
    for (int i = 0; i < HH; i++) {
        float v[4];
        float mx = -3.4e38f;
        #pragma unroll
        for (int j = 0; j < 4; j++) {
            int m = tid + j * 256;
            v[j] = Mm[i * HH + 0] * s[0][m] + Mm[i * HH + 1] * s[1][m]
                 + Mm[i * HH + 2] * s[2][m] + Mm[i * HH + 3] * s[3][m];
            mx = fmaxf(mx, v[j]);
        }
        #pragma unroll
        for (int o = 16; o > 0; o >>= 1) mx = fmaxf(mx, __shfl_xor_sync(0xffffffffu, mx, o));
        if ((tid & 31) == 0) red[tid >> 5] = mx;
        __syncthreads();
        float rmax = red[0];
        #pragma unroll
        for (int w = 1; w < 8; w++) rmax = fmaxf(rmax, red[w]);
        __syncthreads();

        float sum = 0.0f;
        #pragma unroll
        for (int j = 0; j < 4; j++) { v[j] = expf(v[j] - rmax); sum += v[j]; }
        #pragma unroll
        for (int o = 16; o > 0; o >>= 1) sum += __shfl_xor_sync(0xffffffffu, sum, o);
        if ((tid & 31) == 0) red[tid >> 5] = sum;
        __syncthreads();
        float rsum = red[0];
        #pragma unroll
        for (int w = 1; w < 8; w++) rsum += red[w];
        __syncthreads();

        float inv = 1.0f / rsum;
        float* dst = S + ((size_t)(b * HH + i) * NN + n) * NN;
        #pragma unroll
        for (int j = 0; j < 4; j++) dst[tid + j * 256] = v[j] * inv;
    }
}

// ---------------------------------------------------------------------------
extern "C" void kernel_launch(void* const* d_in, const int* in_sizes, int n_in,
                              void* d_out, int out_size)
{
    const float* x      = (const float*)d_in[0];  // [B,N,C]
    const float* w_qkv  = (const float*)d_in[1];  // [3C,C]
    const float* w_proj = (const float*)d_in[2];  // [C,C]
    const float* b_proj = (const float*)d_in[3];  // [C]
    const float* w_main = (const float*)d_in[4];  // [H]
    const float* w_rest = (const float*)d_in[5];  // [H,H-1]
    float* out = (float*)d_out;                   // [B,N,C]

    float* qkv; cudaGetSymbolAddress((void**)&qkv, g_qkv);
    float* S;   cudaGetSymbolAddress((void**)&S,   g_s);
    float* O;   cudaGetSymbolAddress((void**)&O,   g_o);

    // 1) QKV = X @ Wqkv^T : [8192,1536,512]
    tgemm_kernel<true, false><<<dim3(C3 / 128, BN_TOK / 128, 1), 256>>>(
        x, w_qkv, qkv, nullptr,
        CC, CC, CC, C3,
        1, 0, 0, 0, 0, 0, 0, 1.0f);

    // 2) S[b,h] = scale * Q_bh @ K_bh^T : 32 x [1024,1024,128]
    tgemm_kernel<true, false><<<dim3(NN / 128, NN / 128, BB * HH), 256>>>(
        qkv, qkv + CC, S, nullptr,
        HD, C3, C3, NN,
        HH,
        /*sAi*/ HD, /*sAo*/ (long long)NN * C3,
        /*sBi*/ HD, /*sBo*/ (long long)NN * C3,
        /*sCi*/ (long long)NN * NN, /*sCo*/ (long long)HH * NN * NN,
        SCALE);

    // 3) cross-head mix + softmax (in-place over S)
    mix_softmax_kernel<<<BB * NN, 256>>>(S, w_main, w_rest);

    // 4) O[b,h] = P_bh @ V_bh : 32 x [1024,128,1024]
    tgemm_kernel<false, false><<<dim3(HD / 128, NN / 128, BB * HH), 256>>>(
        S, qkv + 2 * CC, O, nullptr,
        NN, NN, C3, CC,
        HH,
        /*sAi*/ (long long)NN * NN, /*sAo*/ (long long)HH * NN * NN,
        /*sBi*/ HD, /*sBo*/ (long long)NN * C3,
        /*sCi*/ HD, /*sCo*/ (long long)NN * CC,
        1.0f);

    // 5) out = O @ Wproj^T + b : [8192,512,512]
    tgemm_kernel<true, true><<<dim3(CC / 128, BN_TOK / 128, 1), 256>>>(
        O, w_proj, out, b_proj,
        CC, CC, CC, CC,
        1, 0, 0, 0, 0, 0, 0, 1.0f);
}

// round 6
// speedup vs baseline: 2.4118x; 1.3584x over previous
#include <cuda_runtime.h>
#include <cuda_bf16.h>
#include <cstdint>

// Problem constants
#define BB   8
#define NN   1024
#define CC   512
#define HH   4
#define HD   128
#define BN_TOK (BB * NN)          // 8192
#define C3  (3 * CC)              // 1536
#define SCALE 0.08838834764831845f  // 128^-0.5

#define NST 3                      // pipeline stages
#define APITCH 20                  // floats per row, A / B(T) tiles ([row][k])
#define BPITCH 136                 // floats per row, B(N) tiles ([k][n])

// Scratch (device globals: no allocation allowed)
__device__ float g_qkv[(size_t)BN_TOK * C3];          // [B*N, 3C]  50.3 MB
__device__ float g_s[(size_t)BB * HH * NN * NN];      // [B,H,N,N]  134 MB (in-place P)
__device__ float g_o[(size_t)BN_TOK * CC];            // [B,N,C]    16.8 MB

__device__ __forceinline__ unsigned f2tf32(float x) {
    unsigned r;
    asm("cvt.rna.tf32.f32 %0, %1;" : "=r"(r) : "f"(x));
    return r;
}

__device__ __forceinline__ void mma_tf32(float* c, const unsigned* a, const unsigned* b) {
    asm volatile(
        "mma.sync.aligned.m16n8k8.row.col.f32.tf32.tf32.f32 "
        "{%0,%1,%2,%3}, {%4,%5,%6,%7}, {%8,%9}, {%0,%1,%2,%3};"
        : "+f"(c[0]), "+f"(c[1]), "+f"(c[2]), "+f"(c[3])
        : "r"(a[0]), "r"(a[1]), "r"(a[2]), "r"(a[3]), "r"(b[0]), "r"(b[1]));
}

__device__ __forceinline__ void cp16(unsigned dst, const void* src) {
    asm volatile("cp.async.cg.shared.global [%0], [%1], 16;" :: "r"(dst), "l"(src));
}
__device__ __forceinline__ void cp_commit() {
    asm volatile("cp.async.commit_group;");
}
__device__ __forceinline__ void cp_wait() {
    asm volatile("cp.async.wait_group %0;" :: "n"(NST - 2));
}

// ---------------------------------------------------------------------------
// tf32 tensor-core GEMM, cp.async 3-stage pipeline.
//   C = alpha * A (.) op(B) (+ bias)
//   TRANSB=true : B is [N,K] row-major (C = A B^T)
//   TRANSB=false: B is [K,N] row-major (C = A B)
// CTA tile 128x128, BK=16 per stage, 256 threads = 8 warps, warp tile 32x64.
// All dims multiples of tile sizes (true for this problem).
// ---------------------------------------------------------------------------
template<bool TRANSB, bool BIAS>
__global__ __launch_bounds__(256) void tgemm_kernel(
    const float* __restrict__ A, const float* __restrict__ B,
    float* __restrict__ C, const float* __restrict__ bias,
    int K, int lda, int ldb, int ldc,
    int bin,
    long long sAi, long long sAo,
    long long sBi, long long sBo,
    long long sCi, long long sCo,
    float alpha)
{
    int z  = blockIdx.z;
    int zi = z % bin, zo = z / bin;
    A += (size_t)zi * sAi + (size_t)zo * sAo;
    B += (size_t)zi * sBi + (size_t)zo * sBo;
    C += (size_t)zi * sCi + (size_t)zo * sCo;

    extern __shared__ float smp[];
    float* AsAll = smp;                                   // [NST][128][APITCH]
    float* BsAll = smp + NST * 128 * APITCH;              // T:[NST][128][APITCH]  N:[NST][16][BPITCH]
    const int BSTG = TRANSB ? 128 * APITCH : 16 * BPITCH;

    const int tid  = threadIdx.x;
    const int lane = tid & 31;
    const int g    = lane >> 2;        // 0..7
    const int tg   = lane & 3;         // 0..3
    const int wm   = (tid >> 5) & 3;   // warp m-index 0..3
    const int wn   = tid >> 7;         // warp n-index 0..1
    const int mbase = wm * 32;
    const int nbase = wn * 64;

    const int rowBase = blockIdx.y * 128;
    const int colBase = blockIdx.x * 128;

    float acc[2][8][4];
    #pragma unroll
    for (int mi = 0; mi < 2; mi++)
        #pragma unroll
        for (int ni = 0; ni < 8; ni++)
            #pragma unroll
            for (int r = 0; r < 4; r++) acc[mi][ni][r] = 0.0f;

    // ---- async stage loaders (128x16 A tile; B tile 128x16 or 16x128) ----
    auto loadStage = [&](int st, int kt) {
        float* Ad = AsAll + st * 128 * APITCH;
        #pragma unroll
        for (int r = 0; r < 2; r++) {
            int c   = r * 256 + tid;
            int row = c >> 2;
            int kq  = (c & 3) << 2;
            cp16((unsigned)__cvta_generic_to_shared(Ad + row * APITCH + kq),
                 A + (size_t)(rowBase + row) * lda + kt + kq);
        }
        float* Bd = BsAll + st * BSTG;
        if (TRANSB) {
            #pragma unroll
            for (int r = 0; r < 2; r++) {
                int c   = r * 256 + tid;
                int row = c >> 2;
                int kq  = (c & 3) << 2;
                cp16((unsigned)__cvta_generic_to_shared(Bd + row * APITCH + kq),
                     B + (size_t)(colBase + row) * ldb + kt + kq);
            }
        } else {
            #pragma unroll
            for (int r = 0; r < 2; r++) {
                int c    = r * 256 + tid;
                int krow = c >> 5;
                int nq   = (c & 31) << 2;
                cp16((unsigned)__cvta_generic_to_shared(Bd + krow * BPITCH + nq),
                     B + (size_t)(kt + krow) * ldb + colBase + nq);
            }
        }
    };

    const int nk = K >> 4;   // 16-k stages
    // prologue: fill NST-1 stages
    loadStage(0, 0);
    cp_commit();
    if (nk > 1) loadStage(1, 16);
    cp_commit();

    int st = 0;
    for (int it = 0; it < nk; it++) {
        cp_wait();          // oldest in-flight group (stage `st`) is complete
        __syncthreads();    // everyone's copies visible; prev compute finished

        // prefetch the stage we will need NST-1 iterations from now
        int ktn = (it + NST - 1) << 4;
        int stn = st + NST - 1; if (stn >= NST) stn -= NST;
        if (ktn < K) loadStage(stn, ktn);
        cp_commit();

        // ---- compute current stage ----
        const float* Asb = AsAll + st * 128 * APITCH;
        const float* Bsb = BsAll + st * BSTG;
        #pragma unroll
        for (int ks = 0; ks < 16; ks += 8) {
            unsigned a[2][4], b[8][2];
            #pragma unroll
            for (int mi = 0; mi < 2; mi++) {
                int m = mbase + mi * 16 + g;
                a[mi][0] = f2tf32(Asb[(size_t)m * APITCH + ks + tg]);
                a[mi][1] = f2tf32(Asb[(size_t)(m + 8) * APITCH + ks + tg]);
                a[mi][2] = f2tf32(Asb[(size_t)m * APITCH + ks + tg + 4]);
                a[mi][3] = f2tf32(Asb[(size_t)(m + 8) * APITCH + ks + tg + 4]);
            }
            #pragma unroll
            for (int ni = 0; ni < 8; ni++) {
                int n = nbase + ni * 8 + g;
                if (TRANSB) {
                    b[ni][0] = f2tf32(Bsb[(size_t)n * APITCH + ks + tg]);
                    b[ni][1] = f2tf32(Bsb[(size_t)n * APITCH + ks + tg + 4]);
                } else {
                    b[ni][0] = f2tf32(Bsb[(size_t)(ks + tg) * BPITCH + n]);
                    b[ni][1] = f2tf32(Bsb[(size_t)(ks + tg + 4) * BPITCH + n]);
                }
            }
            #pragma unroll
            for (int mi = 0; mi < 2; mi++)
                #pragma unroll
                for (int ni = 0; ni < 8; ni++)
                    mma_tf32(acc[mi][ni], a[mi], b[ni]);
        }

        st++; if (st >= NST) st = 0;
        __syncthreads();    // done reading stage before it is overwritten
    }

    // ---- Epilogue ----
    #pragma unroll
    for (int mi = 0; mi < 2; mi++) {
        #pragma unroll
        for (int ni = 0; ni < 8; ni++) {
            int row = rowBase + mbase + mi * 16 + g;
            int col = colBase + nbase + ni * 8 + tg * 2;
            float bx = 0.f, by = 0.f;
            if (BIAS) { bx = bias[col]; by = bias[col + 1]; }
            float2 v0, v1;
            v0.x = alpha * acc[mi][ni][0] + bx;
            v0.y = alpha * acc[mi][ni][1] + by;
            v1.x = alpha * acc[mi][ni][2] + bx;
            v1.y = alpha * acc[mi][ni][3] + by;
            *(float2*)(C + (size_t)row * ldc + col)       = v0;
            *(float2*)(C + (size_t)(row + 8) * ldc + col) = v1;
        }
    }
}

// ---------------------------------------------------------------------------
// Cross-head mix + softmax, in-place over g_s.
// ---------------------------------------------------------------------------
__global__ __launch_bounds__(256) void mix_softmax_kernel(
    float* __restrict__ S,
    const float* __restrict__ w_main,
    const float* __restrict__ w_rest)
{
    __shared__ float s[HH][NN];   // 16 KB
    __shared__ float Mm[HH * HH];
    __shared__ float red[8];

    const int b   = blockIdx.x / NN;
    const int n   = blockIdx.x % NN;
    const int tid = threadIdx.x;

    if (tid < HH * HH) {
        int i = tid / HH, j = tid % HH;
        Mm[tid] = (i == j) ? w_main[i]
                           : w_rest[i * (HH - 1) + (j < i ? j : j - 1)];
    }

    #pragma unroll
    for (int h = 0; h < HH; h++) {
        const float* src = S + ((size_t)(b * HH + h) * NN + n) * NN;
        for (int m = tid; m < NN; m += 256) s[h][m] = src[m];
    }
    __syncthreads();

    #pragma unroll
    for (int i = 0; i < HH; i++) {
        float v[4];
        float mx = -3.4e38f;
        #pragma unroll
        for (int j = 0; j < 4; j++) {
            int m = tid + j * 256;
            v[j] = Mm[i * HH + 0] * s[0][m] + Mm[i * HH + 1] * s[1][m]
                 + Mm[i * HH + 2] * s[2][m] + Mm[i * HH + 3] * s[3][m];
            mx = fmaxf(mx, v[j]);
        }
        #pragma unroll
        for (int o = 16; o > 0; o >>= 1) mx = fmaxf(mx, __shfl_xor_sync(0xffffffffu, mx, o));
        if ((tid & 31) == 0) red[tid >> 5] = mx;
        __syncthreads();
        float rmax = red[0];
        #pragma unroll
        for (int w = 1; w < 8; w++) rmax = fmaxf(rmax, red[w]);
        __syncthreads();

        float sum = 0.0f;
        #pragma unroll
        for (int j = 0; j < 4; j++) { v[j] = expf(v[j] - rmax); sum += v[j]; }
        #pragma unroll
        for (int o = 16; o > 0; o >>= 1) sum += __shfl_xor_sync(0xffffffffu, sum, o);
        if ((tid & 31) == 0) red[tid >> 5] = sum;
        __syncthreads();
        float rsum = red[0];
        #pragma unroll
        for (int w = 1; w < 8; w++) rsum += red[w];
        __syncthreads();

        float inv = 1.0f / rsum;
        float* dst = S + ((size_t)(b * HH + i) * NN + n) * NN;
        #pragma unroll
        for (int j = 0; j < 4; j++) dst[tid + j * 256] = v[j] * inv;
    }
}

// ---------------------------------------------------------------------------
extern "C" void kernel_launch(void* const* d_in, const int* in_sizes, int n_in,
                              void* d_out, int out_size)
{
    const float* x      = (const float*)d_in[0];  // [B,N,C]
    const float* w_qkv  = (const float*)d_in[1];  // [3C,C]
    const float* w_proj = (const float*)d_in[2];  // [C,C]
    const float* b_proj = (const float*)d_in[3];  // [C]
    const float* w_main = (const float*)d_in[4];  // [H]
    const float* w_rest = (const float*)d_in[5];  // [H,H-1]
    float* out = (float*)d_out;                   // [B,N,C]

    float* qkv; cudaGetSymbolAddress((void**)&qkv, g_qkv);
    float* S;   cudaGetSymbolAddress((void**)&S,   g_s);
    float* O;   cudaGetSymbolAddress((void**)&O,   g_o);

    const int SMEM_T = NST * (128 * APITCH + 128 * APITCH) * 4;  // 61440 B
    const int SMEM_N = NST * (128 * APITCH + 16 * BPITCH) * 4;   // 56832 B
    cudaFuncSetAttribute(tgemm_kernel<true,  false>,
                         cudaFuncAttributeMaxDynamicSharedMemorySize, SMEM_T);
    cudaFuncSetAttribute(tgemm_kernel<false, false>,
                         cudaFuncAttributeMaxDynamicSharedMemorySize, SMEM_N);
    cudaFuncSetAttribute(tgemm_kernel<true,  true>,
                         cudaFuncAttributeMaxDynamicSharedMemorySize, SMEM_T);

    // 1) QKV = X @ Wqkv^T : [8192,1536,512]
    tgemm_kernel<true, false><<<dim3(C3 / 128, BN_TOK / 128, 1), 256, SMEM_T>>>(
        x, w_qkv, qkv, nullptr,
        CC, CC, CC, C3,
        1, 0, 0, 0, 0, 0, 0, 1.0f);

    // 2) S[b,h] = scale * Q_bh @ K_bh^T : 32 x [1024,1024,128]
    tgemm_kernel<true, false><<<dim3(NN / 128, NN / 128, BB * HH), 256, SMEM_T>>>(
        qkv, qkv + CC, S, nullptr,
        HD, C3, C3, NN,
        HH,
        /*sAi*/ HD, /*sAo*/ (long long)NN * C3,
        /*sBi*/ HD, /*sBo*/ (long long)NN * C3,
        /*sCi*/ (long long)NN * NN, /*sCo*/ (long long)HH * NN * NN,
        SCALE);

    // 3) cross-head mix + softmax (in-place over S)
    mix_softmax_kernel<<<BB * NN, 256>>>(S, w_main, w_rest);

    // 4) O[b,h] = P_bh @ V_bh : 32 x [1024,128,1024]
    tgemm_kernel<false, false><<<dim3(HD / 128, NN / 128, BB * HH), 256, SMEM_N>>>(
        S, qkv + 2 * CC, O, nullptr,
        NN, NN, C3, CC,
        HH,
        /*sAi*/ (long long)NN * NN, /*sAo*/ (long long)HH * NN * NN,
        /*sBi*/ HD, /*sBo*/ (long long)NN * C3,
        /*sCi*/ HD, /*sCo*/ (long long)NN * CC,
        1.0f);

    // 5) out = O @ Wproj^T + b : [8192,512,512]
    tgemm_kernel<true, true><<<dim3(CC / 128, BN_TOK / 128, 1), 256, SMEM_T>>>(
        O, w_proj, out, b_proj,
        CC, CC, CC, CC,
        1, 0, 0, 0, 0, 0, 0, 1.0f);
}

// round 8
// speedup vs baseline: 2.8162x; 1.1677x over previous
#include <cuda_runtime.h>
#include <cuda_bf16.h>
#include <cstdint>

// Problem constants
#define BB   8
#define NN   1024
#define CC   512
#define HH   4
#define HD   128
#define BN_TOK (BB * NN)          // 8192
#define C3  (3 * CC)              // 1536
#define SCALE 0.08838834764831845f  // 128^-0.5

#define NST 3                      // pipeline stages
#define APITCH 20                  // floats per row, A / B(T) tiles ([row][k])
#define BPITCH 136                 // floats per row, B(N) tiles ([k][n])

// Scratch (device globals: no allocation allowed)
__device__ float g_qkv[(size_t)BN_TOK * C3];          // [B*N, 3C]  tf32-rounded
__device__ float g_s[(size_t)BB * HH * NN * NN];      // [B,H,N,N]  (in-place P)
__device__ float g_o[(size_t)BN_TOK * CC];            // [B,N,C]    tf32-rounded
__device__ float g_xr[(size_t)BN_TOK * CC];           // x  tf32-rounded
__device__ float g_wqkvr[(size_t)C3 * CC];            // w_qkv tf32-rounded
__device__ float g_wprojr[(size_t)CC * CC];           // w_proj tf32-rounded

__device__ __forceinline__ unsigned f2tf32(float x) {
    unsigned r;
    asm("cvt.rna.tf32.f32 %0, %1;" : "=r"(r) : "f"(x));
    return r;
}
__device__ __forceinline__ float rndtf(float x) { return __uint_as_float(f2tf32(x)); }

__device__ __forceinline__ void mma_tf32(float* c, const unsigned* a, const unsigned* b) {
    asm volatile(
        "mma.sync.aligned.m16n8k8.row.col.f32.tf32.tf32.f32 "
        "{%0,%1,%2,%3}, {%4,%5,%6,%7}, {%8,%9}, {%0,%1,%2,%3};"
        : "+f"(c[0]), "+f"(c[1]), "+f"(c[2]), "+f"(c[3])
        : "r"(a[0]), "r"(a[1]), "r"(a[2]), "r"(a[3]), "r"(b[0]), "r"(b[1]));
}

__device__ __forceinline__ void cp16(unsigned dst, const void* src) {
    asm volatile("cp.async.cg.shared.global [%0], [%1], 16;" :: "r"(dst), "l"(src));
}
__device__ __forceinline__ void cp_commit() {
    asm volatile("cp.async.commit_group;");
}
__device__ __forceinline__ void cp_wait() {
    asm volatile("cp.async.wait_group %0;" :: "n"(NST - 2));
}

// ---------------------------------------------------------------------------
// tf32 round prepass: out[i] = tf32(in[i]), float4-wide
// ---------------------------------------------------------------------------
__global__ __launch_bounds__(256) void round_kernel(
    const float* __restrict__ in, float* __restrict__ out, int n4)
{
    int i = blockIdx.x * 256 + threadIdx.x;
    if (i < n4) {
        float4 v = ((const float4*)in)[i];
        v.x = rndtf(v.x); v.y = rndtf(v.y);
        v.z = rndtf(v.z); v.w = rndtf(v.w);
        ((float4*)out)[i] = v;
    }
}

// ---------------------------------------------------------------------------
// tf32 tensor-core GEMM, cp.async 3-stage pipeline. Operands must already be
// tf32-rounded in gmem (low 13 mantissa bits zero) -> no CVT in inner loop.
//   C = alpha * A (.) op(B) (+ bias) [, tf32-rounded output if RND]
//   TRANSB=true : B is [N,K] row-major (C = A B^T)
//   TRANSB=false: B is [K,N] row-major (C = A B)
// CTA tile 128x128, BK=16/stage, 256 threads = 8 warps, warp tile 32x64.
// ---------------------------------------------------------------------------
template<bool TRANSB, bool BIAS, bool RND>
__global__ __launch_bounds__(256) void tgemm_kernel(
    const float* __restrict__ A, const float* __restrict__ B,
    float* __restrict__ C, const float* __restrict__ bias,
    int K, int lda, int ldb, int ldc,
    int bin,
    long long sAi, long long sAo,
    long long sBi, long long sBo,
    long long sCi, long long sCo,
    float alpha)
{
    int z  = blockIdx.z;
    int zi = z % bin, zo = z / bin;
    A += (size_t)zi * sAi + (size_t)zo * sAo;
    B += (size_t)zi * sBi + (size_t)zo * sBo;
    C += (size_t)zi * sCi + (size_t)zo * sCo;

    extern __shared__ float smp[];
    float* AsAll = smp;                                   // [NST][128][APITCH]
    float* BsAll = smp + NST * 128 * APITCH;              // T:[NST][128][APITCH] N:[NST][16][BPITCH]
    const int BSTG = TRANSB ? 128 * APITCH : 16 * BPITCH;

    const int tid  = threadIdx.x;
    const int lane = tid & 31;
    const int g    = lane >> 2;
    const int tg   = lane & 3;
    const int wm   = (tid >> 5) & 3;
    const int wn   = tid >> 7;
    const int mbase = wm * 32;
    const int nbase = wn * 64;

    const int rowBase = blockIdx.y * 128;
    const int colBase = blockIdx.x * 128;

    float acc[2][8][4];
    #pragma unroll
    for (int mi = 0; mi < 2; mi++)
        #pragma unroll
        for (int ni = 0; ni < 8; ni++)
            #pragma unroll
            for (int r = 0; r < 4; r++) acc[mi][ni][r] = 0.0f;

    auto loadStage = [&](int st, int kt) {
        float* Ad = AsAll + st * 128 * APITCH;
        #pragma unroll
        for (int r = 0; r < 2; r++) {
            int c   = r * 256 + tid;
            int row = c >> 2;
            int kq  = (c & 3) << 2;
            cp16((unsigned)__cvta_generic_to_shared(Ad + row * APITCH + kq),
                 A + (size_t)(rowBase + row) * lda + kt + kq);
        }
        float* Bd = BsAll + st * BSTG;
        if (TRANSB) {
            #pragma unroll
            for (int r = 0; r < 2; r++) {
                int c   = r * 256 + tid;
                int row = c >> 2;
                int kq  = (c & 3) << 2;
                cp16((unsigned)__cvta_generic_to_shared(Bd + row * APITCH + kq),
                     B + (size_t)(colBase + row) * ldb + kt + kq);
            }
        } else {
            #pragma unroll
            for (int r = 0; r < 2; r++) {
                int c    = r * 256 + tid;
                int krow = c >> 5;
                int nq   = (c & 31) << 2;
                cp16((unsigned)__cvta_generic_to_shared(Bd + krow * BPITCH + nq),
                     B + (size_t)(kt + krow) * ldb + colBase + nq);
            }
        }
    };

    const int nk = K >> 4;
    loadStage(0, 0);
    cp_commit();
    if (nk > 1) loadStage(1, 16);
    cp_commit();

    int st = 0;
    for (int it = 0; it < nk; it++) {
        cp_wait();
        __syncthreads();

        int ktn = (it + NST - 1) << 4;
        int stn = st + NST - 1; if (stn >= NST) stn -= NST;
        if (ktn < K) loadStage(stn, ktn);
        cp_commit();

        const float* Asb = AsAll + st * 128 * APITCH;
        const float* Bsb = BsAll + st * BSTG;
        #pragma unroll
        for (int ks = 0; ks < 16; ks += 8) {
            unsigned a[2][4], b[8][2];
            #pragma unroll
            for (int mi = 0; mi < 2; mi++) {
                int m = mbase + mi * 16 + g;
                a[mi][0] = __float_as_uint(Asb[(size_t)m * APITCH + ks + tg]);
                a[mi][1] = __float_as_uint(Asb[(size_t)(m + 8) * APITCH + ks + tg]);
                a[mi][2] = __float_as_uint(Asb[(size_t)m * APITCH + ks + tg + 4]);
                a[mi][3] = __float_as_uint(Asb[(size_t)(m + 8) * APITCH + ks + tg + 4]);
            }
            #pragma unroll
            for (int ni = 0; ni < 8; ni++) {
                int n = nbase + ni * 8 + g;
                if (TRANSB) {
                    b[ni][0] = __float_as_uint(Bsb[(size_t)n * APITCH + ks + tg]);
                    b[ni][1] = __float_as_uint(Bsb[(size_t)n * APITCH + ks + tg + 4]);
                } else {
                    b[ni][0] = __float_as_uint(Bsb[(size_t)(ks + tg) * BPITCH + n]);
                    b[ni][1] = __float_as_uint(Bsb[(size_t)(ks + tg + 4) * BPITCH + n]);
                }
            }
            #pragma unroll
            for (int mi = 0; mi < 2; mi++)
                #pragma unroll
                for (int ni = 0; ni < 8; ni++)
                    mma_tf32(acc[mi][ni], a[mi], b[ni]);
        }

        st++; if (st >= NST) st = 0;
        __syncthreads();
    }

    // ---- Epilogue ----
    #pragma unroll
    for (int mi = 0; mi < 2; mi++) {
        #pragma unroll
        for (int ni = 0; ni < 8; ni++) {
            int row = rowBase + mbase + mi * 16 + g;
            int col = colBase + nbase + ni * 8 + tg * 2;
            float bx = 0.f, by = 0.f;
            if (BIAS) { bx = bias[col]; by = bias[col + 1]; }
            float2 v0, v1;
            v0.x = alpha * acc[mi][ni][0] + bx;
            v0.y = alpha * acc[mi][ni][1] + by;
            v1.x = alpha * acc[mi][ni][2] + bx;
            v1.y = alpha * acc[mi][ni][3] + by;
            if (RND) {
                v0.x = rndtf(v0.x); v0.y = rndtf(v0.y);
                v1.x = rndtf(v1.x); v1.y = rndtf(v1.y);
            }
            *(float2*)(C + (size_t)row * ldc + col)       = v0;
            *(float2*)(C + (size_t)(row + 8) * ldc + col) = v1;
        }
    }
}

// ---------------------------------------------------------------------------
// Cross-head mix + softmax, in-place over g_s. Mix is elementwise in m, so
// no smem staging: each thread loads float4 from each of the 4 head rows,
// mixes in registers, block-reduces max/sum, writes 4 tf32-rounded rows.
// One CTA per (b, n), 256 threads, 3 barriers.
// ---------------------------------------------------------------------------
__global__ __launch_bounds__(256) void mix_softmax_kernel(
    float* __restrict__ S,
    const float* __restrict__ w_main,
    const float* __restrict__ w_rest)
{
    __shared__ float Mm[16];
    __shared__ float redA[4][8];
    __shared__ float redB[4][8];

    const int b    = blockIdx.x / NN;
    const int n    = blockIdx.x % NN;
    const int tid  = threadIdx.x;
    const int lane = tid & 31;
    const int wrp  = tid >> 5;

    if (tid < 16) {
        int i = tid >> 2, j = tid & 3;
        Mm[tid] = (i == j) ? w_main[i]
                           : w_rest[i * (HH - 1) + (j < i ? j : j - 1)];
    }
    __syncthreads();

    const size_t base = ((size_t)b * HH * NN + n) * NN + tid * 4;

    float4 sv[HH];
    #pragma unroll
    for (int h = 0; h < HH; h++)
        sv[h] = *(const float4*)(S + base + (size_t)h * NN * NN);

    float4 v[HH];
    float mx[HH];
    #pragma unroll
    for (int i = 0; i < HH; i++) {
        float m0 = Mm[i*4+0], m1 = Mm[i*4+1], m2 = Mm[i*4+2], m3 = Mm[i*4+3];
        v[i].x = m0*sv[0].x + m1*sv[1].x + m2*sv[2].x + m3*sv[3].x;
        v[i].y = m0*sv[0].y + m1*sv[1].y + m2*sv[2].y + m3*sv[3].y;
        v[i].z = m0*sv[0].z + m1*sv[1].z + m2*sv[2].z + m3*sv[3].z;
        v[i].w = m0*sv[0].w + m1*sv[1].w + m2*sv[2].w + m3*sv[3].w;
        mx[i] = fmaxf(fmaxf(v[i].x, v[i].y), fmaxf(v[i].z, v[i].w));
        #pragma unroll
        for (int o = 16; o > 0; o >>= 1)
            mx[i] = fmaxf(mx[i], __shfl_xor_sync(0xffffffffu, mx[i], o));
    }
    if (lane == 0) {
        #pragma unroll
        for (int i = 0; i < HH; i++) redA[i][wrp] = mx[i];
    }
    __syncthreads();

    float sm[HH];
    #pragma unroll
    for (int i = 0; i < HH; i++) {
        float rmax = redA[i][0];
        #pragma unroll
        for (int w = 1; w < 8; w++) rmax = fmaxf(rmax, redA[i][w]);
        v[i].x = expf(v[i].x - rmax);
        v[i].y = expf(v[i].y - rmax);
        v[i].z = expf(v[i].z - rmax);
        v[i].w = expf(v[i].w - rmax);
        sm[i] = (v[i].x + v[i].y) + (v[i].z + v[i].w);
        #pragma unroll
        for (int o = 16; o > 0; o >>= 1)
            sm[i] += __shfl_xor_sync(0xffffffffu, sm[i], o);
    }
    if (lane == 0) {
        #pragma unroll
        for (int i = 0; i < HH; i++) redB[i][wrp] = sm[i];
    }
    __syncthreads();

    #pragma unroll
    for (int i = 0; i < HH; i++) {
        float rsum = redB[i][0];
        #pragma unroll
        for (int w = 1; w < 8; w++) rsum += redB[i][w];
        float inv = 1.0f / rsum;
        float4 o;
        o.x = rndtf(v[i].x * inv);
        o.y = rndtf(v[i].y * inv);
        o.z = rndtf(v[i].z * inv);
        o.w = rndtf(v[i].w * inv);
        *(float4*)(S + base + (size_t)i * NN * NN) = o;
    }
}

// ---------------------------------------------------------------------------
extern "C" void kernel_launch(void* const* d_in, const int* in_sizes, int n_in,
                              void* d_out, int out_size)
{
    const float* x      = (const float*)d_in[0];  // [B,N,C]
    const float* w_qkv  = (const float*)d_in[1];  // [3C,C]
    const float* w_proj = (const float*)d_in[2];  // [C,C]
    const float* b_proj = (const float*)d_in[3];  // [C]
    const float* w_main = (const float*)d_in[4];  // [H]
    const float* w_rest = (const float*)d_in[5];  // [H,H-1]
    float* out = (float*)d_out;                   // [B,N,C]

    float* qkv; cudaGetSymbolAddress((void**)&qkv, g_qkv);
    float* S;   cudaGetSymbolAddress((void**)&S,   g_s);
    float* O;   cudaGetSymbolAddress((void**)&O,   g_o);
    float* xr;  cudaGetSymbolAddress((void**)&xr,  g_xr);
    float* wq;  cudaGetSymbolAddress((void**)&wq,  g_wqkvr);
    float* wp;  cudaGetSymbolAddress((void**)&wp,  g_wprojr);

    const int SMEM_T = NST * (128 * APITCH + 128 * APITCH) * 4;  // 61440 B
    const int SMEM_N = NST * (128 * APITCH + 16 * BPITCH) * 4;   // 56832 B
    cudaFuncSetAttribute(tgemm_kernel<true,  false, true >,
                         cudaFuncAttributeMaxDynamicSharedMemorySize, SMEM_T);
    cudaFuncSetAttribute(tgemm_kernel<true,  false, false>,
                         cudaFuncAttributeMaxDynamicSharedMemorySize, SMEM_T);
    cudaFuncSetAttribute(tgemm_kernel<false, false, true >,
                         cudaFuncAttributeMaxDynamicSharedMemorySize, SMEM_N);
    cudaFuncSetAttribute(tgemm_kernel<true,  true,  false>,
                         cudaFuncAttributeMaxDynamicSharedMemorySize, SMEM_T);

    // 0) tf32-round inputs into scratch
    round_kernel<<<(BN_TOK * CC / 4) / 256, 256>>>(x, xr, BN_TOK * CC / 4);
    round_kernel<<<(C3 * CC / 4) / 256, 256>>>(w_qkv, wq, C3 * CC / 4);
    round_kernel<<<(CC * CC / 4) / 256, 256>>>(w_proj, wp, CC * CC / 4);

    // 1) QKV = Xr @ Wqkv_r^T  (output tf32-rounded)
    tgemm_kernel<true, false, true><<<dim3(C3 / 128, BN_TOK / 128, 1), 256, SMEM_T>>>(
        xr, wq, qkv, nullptr,
        CC, CC, CC, C3,
        1, 0, 0, 0, 0, 0, 0, 1.0f);

    // 2) S[b,h] = scale * Q_bh @ K_bh^T : 32 x [1024,1024,128]
    tgemm_kernel<true, false, false><<<dim3(NN / 128, NN / 128, BB * HH), 256, SMEM_T>>>(
        qkv, qkv + CC, S, nullptr,
        HD, C3, C3, NN,
        HH,
        /*sAi*/ HD, /*sAo*/ (long long)NN * C3,
        /*sBi*/ HD, /*sBo*/ (long long)NN * C3,
        /*sCi*/ (long long)NN * NN, /*sCo*/ (long long)HH * NN * NN,
        SCALE);

    // 3) cross-head mix + softmax (in-place, P tf32-rounded)
    mix_softmax_kernel<<<BB * NN, 256>>>(S, w_main, w_rest);

    // 4) O[b,h] = P_bh @ V_bh : 32 x [1024,128,1024] (output tf32-rounded)
    tgemm_kernel<false, false, true><<<dim3(HD / 128, NN / 128, BB * HH), 256, SMEM_N>>>(
        S, qkv + 2 * CC, O, nullptr,
        NN, NN, C3, CC,
        HH,
        /*sAi*/ (long long)NN * NN, /*sAo*/ (long long)HH * NN * NN,
        /*sBi*/ HD, /*sBo*/ (long long)NN * C3,
        /*sCi*/ HD, /*sCo*/ (long long)NN * CC,
        1.0f);

    // 5) out = O @ Wproj_r^T + b : [8192,512,512] (full fp32 output)
    tgemm_kernel<true, true, false><<<dim3(CC / 128, BN_TOK / 128, 1), 256, SMEM_T>>>(
        O, wp, out, b_proj,
        CC, CC, CC, CC,
        1, 0, 0, 0, 0, 0, 0, 1.0f);
}

// round 9
// speedup vs baseline: 2.8450x; 1.0102x over previous
#include <cuda_runtime.h>
#include <cuda_bf16.h>
#include <cstdint>

// Problem constants
#define BB   8
#define NN   1024
#define CC   512
#define HH   4
#define HD   128
#define BN_TOK (BB * NN)          // 8192
#define C3  (3 * CC)              // 1536
#define SCALE 0.08838834764831845f  // 128^-0.5

#define NST 3                      // pipeline stages
#define BK  32                     // k per stage
#define APITCH 36                  // floats per row, A / B(T) tiles ([row][k]), 32+4 pad
#define BPITCH 136                 // floats per row, B(N) tiles ([k][n])

// Scratch (device globals: no allocation allowed)
__device__ float g_qkv[(size_t)BN_TOK * C3];          // [B*N, 3C]  tf32-rounded
__device__ float g_s[(size_t)BB * HH * NN * NN];      // [B,H,N,N]  (in-place P)
__device__ float g_o[(size_t)BN_TOK * CC];            // [B,N,C]    tf32-rounded
__device__ float g_xr[(size_t)BN_TOK * CC];           // x  tf32-rounded
__device__ float g_wqkvr[(size_t)C3 * CC];            // w_qkv tf32-rounded
__device__ float g_wprojr[(size_t)CC * CC];           // w_proj tf32-rounded

__device__ __forceinline__ unsigned f2tf32(float x) {
    unsigned r;
    asm("cvt.rna.tf32.f32 %0, %1;" : "=r"(r) : "f"(x));
    return r;
}
__device__ __forceinline__ float rndtf(float x) { return __uint_as_float(f2tf32(x)); }

__device__ __forceinline__ void mma_tf32(float* c, const unsigned* a, const unsigned* b) {
    asm volatile(
        "mma.sync.aligned.m16n8k8.row.col.f32.tf32.tf32.f32 "
        "{%0,%1,%2,%3}, {%4,%5,%6,%7}, {%8,%9}, {%0,%1,%2,%3};"
        : "+f"(c[0]), "+f"(c[1]), "+f"(c[2]), "+f"(c[3])
        : "r"(a[0]), "r"(a[1]), "r"(a[2]), "r"(a[3]), "r"(b[0]), "r"(b[1]));
}

__device__ __forceinline__ void cp16(unsigned dst, const void* src) {
    asm volatile("cp.async.cg.shared.global [%0], [%1], 16;" :: "r"(dst), "l"(src));
}
__device__ __forceinline__ void cp_commit() {
    asm volatile("cp.async.commit_group;");
}
__device__ __forceinline__ void cp_wait() {
    asm volatile("cp.async.wait_group %0;" :: "n"(NST - 2));
}

// ---------------------------------------------------------------------------
// tf32 round prepass: out[i] = tf32(in[i]), float4-wide
// ---------------------------------------------------------------------------
__global__ __launch_bounds__(256) void round_kernel(
    const float* __restrict__ in, float* __restrict__ out, int n4)
{
    int i = blockIdx.x * 256 + threadIdx.x;
    if (i < n4) {
        float4 v = ((const float4*)in)[i];
        v.x = rndtf(v.x); v.y = rndtf(v.y);
        v.z = rndtf(v.z); v.w = rndtf(v.w);
        ((float4*)out)[i] = v;
    }
}

// ---------------------------------------------------------------------------
// tf32 tensor-core GEMM, cp.async 3-stage pipeline, BK=32 per stage,
// ONE __syncthreads per stage. Operands must already be tf32-rounded in gmem.
//   C = alpha * A (.) op(B) (+ bias) [, tf32-rounded output if RND]
//   TRANSB=true : B is [N,K] row-major (C = A B^T)
//   TRANSB=false: B is [K,N] row-major (C = A B)
// CTA tile 128x128, 256 threads = 8 warps, warp tile 32x64.
// ---------------------------------------------------------------------------
template<bool TRANSB, bool BIAS, bool RND>
__global__ __launch_bounds__(256) void tgemm_kernel(
    const float* __restrict__ A, const float* __restrict__ B,
    float* __restrict__ C, const float* __restrict__ bias,
    int K, int lda, int ldb, int ldc,
    int bin,
    long long sAi, long long sAo,
    long long sBi, long long sBo,
    long long sCi, long long sCo,
    float alpha)
{
    int z  = blockIdx.z;
    int zi = z % bin, zo = z / bin;
    A += (size_t)zi * sAi + (size_t)zo * sAo;
    B += (size_t)zi * sBi + (size_t)zo * sBo;
    C += (size_t)zi * sCi + (size_t)zo * sCo;

    extern __shared__ float smp[];
    float* AsAll = smp;                                   // [NST][128][APITCH]
    float* BsAll = smp + NST * 128 * APITCH;              // T:[NST][128][APITCH] N:[NST][32][BPITCH]
    const int BSTG = TRANSB ? 128 * APITCH : 32 * BPITCH;

    const int tid  = threadIdx.x;
    const int lane = tid & 31;
    const int g    = lane >> 2;
    const int tg   = lane & 3;
    const int wm   = (tid >> 5) & 3;
    const int wn   = tid >> 7;
    const int mbase = wm * 32;
    const int nbase = wn * 64;

    const int rowBase = blockIdx.y * 128;
    const int colBase = blockIdx.x * 128;

    float acc[2][8][4];
    #pragma unroll
    for (int mi = 0; mi < 2; mi++)
        #pragma unroll
        for (int ni = 0; ni < 8; ni++)
            #pragma unroll
            for (int r = 0; r < 4; r++) acc[mi][ni][r] = 0.0f;

    // ---- stage loader: A 128x32, B 128x32 (T) or 32x128 (N) ----
    auto loadStage = [&](int st, int kt) {
        float* Ad = AsAll + st * 128 * APITCH;
        #pragma unroll
        for (int r = 0; r < 4; r++) {
            int c   = r * 256 + tid;
            int row = c >> 3;                // 8 chunks per 32-float row
            int kq  = (c & 7) << 2;
            cp16((unsigned)__cvta_generic_to_shared(Ad + row * APITCH + kq),
                 A + (size_t)(rowBase + row) * lda + kt + kq);
        }
        float* Bd = BsAll + st * BSTG;
        if (TRANSB) {
            #pragma unroll
            for (int r = 0; r < 4; r++) {
                int c   = r * 256 + tid;
                int row = c >> 3;
                int kq  = (c & 7) << 2;
                cp16((unsigned)__cvta_generic_to_shared(Bd + row * APITCH + kq),
                     B + (size_t)(colBase + row) * ldb + kt + kq);
            }
        } else {
            #pragma unroll
            for (int r = 0; r < 4; r++) {
                int c    = r * 256 + tid;
                int krow = c >> 5;           // 32 chunks per 128-float row
                int nq   = (c & 31) << 2;
                cp16((unsigned)__cvta_generic_to_shared(Bd + krow * BPITCH + nq),
                     B + (size_t)(kt + krow) * ldb + colBase + nq);
            }
        }
    };

    const int nk = K >> 5;   // 32-k stages
    loadStage(0, 0);
    cp_commit();
    if (nk > 1) loadStage(1, BK);
    cp_commit();

    int st = 0;
    for (int it = 0; it < nk; it++) {
        cp_wait();
        __syncthreads();     // stage `st` complete+visible; all warps done reading
                             // the stage about to be overwritten below (WAR safe)

        int ktn = (it + NST - 1) << 5;
        int stn = st + NST - 1; if (stn >= NST) stn -= NST;
        if (ktn < K) loadStage(stn, ktn);
        cp_commit();

        const float* Asb = AsAll + st * 128 * APITCH;
        const float* Bsb = BsAll + st * BSTG;
        #pragma unroll
        for (int ks = 0; ks < BK; ks += 8) {
            unsigned a[2][4], b[8][2];
            #pragma unroll
            for (int mi = 0; mi < 2; mi++) {
                int m = mbase + mi * 16 + g;
                a[mi][0] = __float_as_uint(Asb[(size_t)m * APITCH + ks + tg]);
                a[mi][1] = __float_as_uint(Asb[(size_t)(m + 8) * APITCH + ks + tg]);
                a[mi][2] = __float_as_uint(Asb[(size_t)m * APITCH + ks + tg + 4]);
                a[mi][3] = __float_as_uint(Asb[(size_t)(m + 8) * APITCH + ks + tg + 4]);
            }
            #pragma unroll
            for (int ni = 0; ni < 8; ni++) {
                int n = nbase + ni * 8 + g;
                if (TRANSB) {
                    b[ni][0] = __float_as_uint(Bsb[(size_t)n * APITCH + ks + tg]);
                    b[ni][1] = __float_as_uint(Bsb[(size_t)n * APITCH + ks + tg + 4]);
                } else {
                    b[ni][0] = __float_as_uint(Bsb[(size_t)(ks + tg) * BPITCH + n]);
                    b[ni][1] = __float_as_uint(Bsb[(size_t)(ks + tg + 4) * BPITCH + n]);
                }
            }
            #pragma unroll
            for (int mi = 0; mi < 2; mi++)
                #pragma unroll
                for (int ni = 0; ni < 8; ni++)
                    mma_tf32(acc[mi][ni], a[mi], b[ni]);
        }

        st++; if (st >= NST) st = 0;
        // no trailing barrier: next iteration's top barrier provides WAR + visibility
    }

    // ---- Epilogue ----
    #pragma unroll
    for (int mi = 0; mi < 2; mi++) {
        #pragma unroll
        for (int ni = 0; ni < 8; ni++) {
            int row = rowBase + mbase + mi * 16 + g;
            int col = colBase + nbase + ni * 8 + tg * 2;
            float bx = 0.f, by = 0.f;
            if (BIAS) { bx = bias[col]; by = bias[col + 1]; }
            float2 v0, v1;
            v0.x = alpha * acc[mi][ni][0] + bx;
            v0.y = alpha * acc[mi][ni][1] + by;
            v1.x = alpha * acc[mi][ni][2] + bx;
            v1.y = alpha * acc[mi][ni][3] + by;
            if (RND) {
                v0.x = rndtf(v0.x); v0.y = rndtf(v0.y);
                v1.x = rndtf(v1.x); v1.y = rndtf(v1.y);
            }
            *(float2*)(C + (size_t)row * ldc + col)       = v0;
            *(float2*)(C + (size_t)(row + 8) * ldc + col) = v1;
        }
    }
}

// ---------------------------------------------------------------------------
// Cross-head mix + softmax, in-place over g_s. Elementwise mix in registers,
// 3 barriers, float4 I/O. One CTA per (b, n), 256 threads.
// ---------------------------------------------------------------------------
__global__ __launch_bounds__(256) void mix_softmax_kernel(
    float* __restrict__ S,
    const float* __restrict__ w_main,
    const float* __restrict__ w_rest)
{
    __shared__ float Mm[16];
    __shared__ float redA[4][8];
    __shared__ float redB[4][8];

    const int b    = blockIdx.x / NN;
    const int n    = blockIdx.x % NN;
    const int tid  = threadIdx.x;
    const int lane = tid & 31;
    const int wrp  = tid >> 5;

    if (tid < 16) {
        int i = tid >> 2, j = tid & 3;
        Mm[tid] = (i == j) ? w_main[i]
                           : w_rest[i * (HH - 1) + (j < i ? j : j - 1)];
    }
    __syncthreads();

    const size_t base = ((size_t)b * HH * NN + n) * NN + tid * 4;

    float4 sv[HH];
    #pragma unroll
    for (int h = 0; h < HH; h++)
        sv[h] = *(const float4*)(S + base + (size_t)h * NN * NN);

    float4 v[HH];
    float mx[HH];
    #pragma unroll
    for (int i = 0; i < HH; i++) {
        float m0 = Mm[i*4+0], m1 = Mm[i*4+1], m2 = Mm[i*4+2], m3 = Mm[i*4+3];
        v[i].x = m0*sv[0].x + m1*sv[1].x + m2*sv[2].x + m3*sv[3].x;
        v[i].y = m0*sv[0].y + m1*sv[1].y + m2*sv[2].y + m3*sv[3].y;
        v[i].z = m0*sv[0].z + m1*sv[1].z + m2*sv[2].z + m3*sv[3].z;
        v[i].w = m0*sv[0].w + m1*sv[1].w + m2*sv[2].w + m3*sv[3].w;
        mx[i] = fmaxf(fmaxf(v[i].x, v[i].y), fmaxf(v[i].z, v[i].w));
        #pragma unroll
        for (int o = 16; o > 0; o >>= 1)
            mx[i] = fmaxf(mx[i], __shfl_xor_sync(0xffffffffu, mx[i], o));
    }
    if (lane == 0) {
        #pragma unroll
        for (int i = 0; i < HH; i++) redA[i][wrp] = mx[i];
    }
    __syncthreads();

    float sm[HH];
    #pragma unroll
    for (int i = 0; i < HH; i++) {
        float rmax = redA[i][0];
        #pragma unroll
        for (int w = 1; w < 8; w++) rmax = fmaxf(rmax, redA[i][w]);
        v[i].x = expf(v[i].x - rmax);
        v[i].y = expf(v[i].y - rmax);
        v[i].z = expf(v[i].z - rmax);
        v[i].w = expf(v[i].w - rmax);
        sm[i] = (v[i].x + v[i].y) + (v[i].z + v[i].w);
        #pragma unroll
        for (int o = 16; o > 0; o >>= 1)
            sm[i] += __shfl_xor_sync(0xffffffffu, sm[i], o);
    }
    if (lane == 0) {
        #pragma unroll
        for (int i = 0; i < HH; i++) redB[i][wrp] = sm[i];
    }
    __syncthreads();

    #pragma unroll
    for (int i = 0; i < HH; i++) {
        float rsum = redB[i][0];
        #pragma unroll
        for (int w = 1; w < 8; w++) rsum += redB[i][w];
        float inv = 1.0f / rsum;
        float4 o;
        o.x = rndtf(v[i].x * inv);
        o.y = rndtf(v[i].y * inv);
        o.z = rndtf(v[i].z * inv);
        o.w = rndtf(v[i].w * inv);
        *(float4*)(S + base + (size_t)i * NN * NN) = o;
    }
}

// ---------------------------------------------------------------------------
extern "C" void kernel_launch(void* const* d_in, const int* in_sizes, int n_in,
                              void* d_out, int out_size)
{
    const float* x      = (const float*)d_in[0];  // [B,N,C]
    const float* w_qkv  = (const float*)d_in[1];  // [3C,C]
    const float* w_proj = (const float*)d_in[2];  // [C,C]
    const float* b_proj = (const float*)d_in[3];  // [C]
    const float* w_main = (const float*)d_in[4];  // [H]
    const float* w_rest = (const float*)d_in[5];  // [H,H-1]
    float* out = (float*)d_out;                   // [B,N,C]

    float* qkv; cudaGetSymbolAddress((void**)&qkv, g_qkv);
    float* S;   cudaGetSymbolAddress((void**)&S,   g_s);
    float* O;   cudaGetSymbolAddress((void**)&O,   g_o);
    float* xr;  cudaGetSymbolAddress((void**)&xr,  g_xr);
    float* wq;  cudaGetSymbolAddress((void**)&wq,  g_wqkvr);
    float* wp;  cudaGetSymbolAddress((void**)&wp,  g_wprojr);

    const int SMEM_T = NST * (128 * APITCH * 2) * 4;              // 110592 B
    const int SMEM_N = NST * (128 * APITCH + 32 * BPITCH) * 4;    // 107520 B
    cudaFuncSetAttribute(tgemm_kernel<true,  false, true >,
                         cudaFuncAttributeMaxDynamicSharedMemorySize, SMEM_T);
    cudaFuncSetAttribute(tgemm_kernel<true,  false, false>,
                         cudaFuncAttributeMaxDynamicSharedMemorySize, SMEM_T);
    cudaFuncSetAttribute(tgemm_kernel<false, false, true >,
                         cudaFuncAttributeMaxDynamicSharedMemorySize, SMEM_N);
    cudaFuncSetAttribute(tgemm_kernel<true,  true,  false>,
                         cudaFuncAttributeMaxDynamicSharedMemorySize, SMEM_T);

    // 0) tf32-round inputs into scratch
    round_kernel<<<(BN_TOK * CC / 4) / 256, 256>>>(x, xr, BN_TOK * CC / 4);
    round_kernel<<<(C3 * CC / 4) / 256, 256>>>(w_qkv, wq, C3 * CC / 4);
    round_kernel<<<(CC * CC / 4) / 256, 256>>>(w_proj, wp, CC * CC / 4);

    // 1) QKV = Xr @ Wqkv_r^T  (output tf32-rounded)
    tgemm_kernel<true, false, true><<<dim3(C3 / 128, BN_TOK / 128, 1), 256, SMEM_T>>>(
        xr, wq, qkv, nullptr,
        CC, CC, CC, C3,
        1, 0, 0, 0, 0, 0, 0, 1.0f);

    // 2) S[b,h] = scale * Q_bh @ K_bh^T : 32 x [1024,1024,128]
    tgemm_kernel<true, false, false><<<dim3(NN / 128, NN / 128, BB * HH), 256, SMEM_T>>>(
        qkv, qkv + CC, S, nullptr,
        HD, C3, C3, NN,
        HH,
        /*sAi*/ HD, /*sAo*/ (long long)NN * C3,
        /*sBi*/ HD, /*sBo*/ (long long)NN * C3,
        /*sCi*/ (long long)NN * NN, /*sCo*/ (long long)HH * NN * NN,
        SCALE);

    // 3) cross-head mix + softmax (in-place, P tf32-rounded)
    mix_softmax_kernel<<<BB * NN, 256>>>(S, w_main, w_rest);

    // 4) O[b,h] = P_bh @ V_bh : 32 x [1024,128,1024] (output tf32-rounded)
    tgemm_kernel<false, false, true><<<dim3(HD / 128, NN / 128, BB * HH), 256, SMEM_N>>>(
        S, qkv + 2 * CC, O, nullptr,
        NN, NN, C3, CC,
        HH,
        /*sAi*/ (long long)NN * NN, /*sAo*/ (long long)HH * NN * NN,
        /*sBi*/ HD, /*sBo*/ (long long)NN * C3,
        /*sCi*/ HD, /*sCo*/ (long long)NN * CC,
        1.0f);

    // 5) out = O @ Wproj_r^T + b : [8192,512,512] (full fp32 output)
    tgemm_kernel<true, true, false><<<dim3(CC / 128, BN_TOK / 128, 1), 256, SMEM_T>>>(
        O, wp, out, b_proj,
        CC, CC, CC, CC,
        1, 0, 0, 0, 0, 0, 0, 1.0f);
}

// round 10
// speedup vs baseline: 3.1843x; 1.1193x over previous
#include <cuda_runtime.h>
#include <cuda_bf16.h>
#include <cstdint>

// Problem constants
#define BB   8
#define NN   1024
#define CC   512
#define HH   4
#define HD   128
#define BN_TOK (BB * NN)          // 8192
#define C3  (3 * CC)              // 1536
#define SCALE 0.08838834764831845f  // 128^-0.5

#define NST 3                      // pipeline stages
#define BK  32                     // k per stage
#define APITCH 36                  // floats per row, A / B(T) tiles ([row][k]), 32+4 pad
#define BPITCH 136                 // floats per row, B(N) tiles ([k][n])

// Scratch (device globals: no allocation allowed)
__device__ float g_qkv[(size_t)BN_TOK * C3];          // [B*N, 3C]  tf32-rounded
__device__ float g_s[(size_t)BB * HH * NN * NN];      // [B,H,N,N]  (in-place P)
__device__ float g_o[(size_t)BN_TOK * CC];            // [B,N,C]    tf32-rounded
__device__ float g_xr[(size_t)BN_TOK * CC];           // x  tf32-rounded
__device__ float g_wqkvr[(size_t)C3 * CC];            // w_qkv tf32-rounded
__device__ float g_wprojr[(size_t)CC * CC];           // w_proj tf32-rounded

__device__ __forceinline__ unsigned f2tf32(float x) {
    unsigned r;
    asm("cvt.rna.tf32.f32 %0, %1;" : "=r"(r) : "f"(x));
    return r;
}
__device__ __forceinline__ float rndtf(float x) { return __uint_as_float(f2tf32(x)); }

__device__ __forceinline__ void mma_tf32(float* c, const unsigned* a, const unsigned* b) {
    asm volatile(
        "mma.sync.aligned.m16n8k8.row.col.f32.tf32.tf32.f32 "
        "{%0,%1,%2,%3}, {%4,%5,%6,%7}, {%8,%9}, {%0,%1,%2,%3};"
        : "+f"(c[0]), "+f"(c[1]), "+f"(c[2]), "+f"(c[3])
        : "r"(a[0]), "r"(a[1]), "r"(a[2]), "r"(a[3]), "r"(b[0]), "r"(b[1]));
}

__device__ __forceinline__ void cp16(unsigned dst, const void* src) {
    asm volatile("cp.async.cg.shared.global [%0], [%1], 16;" :: "r"(dst), "l"(src));
}
__device__ __forceinline__ void cp_commit() {
    asm volatile("cp.async.commit_group;");
}
__device__ __forceinline__ void cp_wait() {
    asm volatile("cp.async.wait_group %0;" :: "n"(NST - 2));
}

// ---------------------------------------------------------------------------
// tf32 round prepass: out[i] = tf32(in[i]), float4-wide
// ---------------------------------------------------------------------------
__global__ __launch_bounds__(256) void round_kernel(
    const float* __restrict__ in, float* __restrict__ out, int n4)
{
    int i = blockIdx.x * 256 + threadIdx.x;
    if (i < n4) {
        float4 v = ((const float4*)in)[i];
        v.x = rndtf(v.x); v.y = rndtf(v.y);
        v.z = rndtf(v.z); v.w = rndtf(v.w);
        ((float4*)out)[i] = v;
    }
}

// ---------------------------------------------------------------------------
// tf32 tensor-core GEMM, cp.async 3-stage pipeline, BK=32 per stage,
// ONE __syncthreads per stage. __launch_bounds__(256,2) pins regs<=128 so
// 2 CTAs/SM stay resident (round-9 regression: 150 regs -> 1 CTA/SM).
//   C = alpha * A (.) op(B) (+ bias) [, tf32-rounded output if RND]
//   TRANSB=true : B is [N,K] row-major (C = A B^T)
//   TRANSB=false: B is [K,N] row-major (C = A B)
// CTA tile 128x128, 256 threads = 8 warps, warp tile 32x64.
// ---------------------------------------------------------------------------
template<bool TRANSB, bool BIAS, bool RND>
__global__ __launch_bounds__(256, 2) void tgemm_kernel(
    const float* __restrict__ A, const float* __restrict__ B,
    float* __restrict__ C, const float* __restrict__ bias,
    int K, int lda, int ldb, int ldc,
    int bin,
    long long sAi, long long sAo,
    long long sBi, long long sBo,
    long long sCi, long long sCo,
    float alpha)
{
    int z  = blockIdx.z;
    int zi = z % bin, zo = z / bin;
    A += (size_t)zi * sAi + (size_t)zo * sAo;
    B += (size_t)zi * sBi + (size_t)zo * sBo;
    C += (size_t)zi * sCi + (size_t)zo * sCo;

    extern __shared__ float smp[];
    float* AsAll = smp;                                   // [NST][128][APITCH]
    float* BsAll = smp + NST * 128 * APITCH;              // T:[NST][128][APITCH] N:[NST][32][BPITCH]
    const int BSTG = TRANSB ? 128 * APITCH : 32 * BPITCH;

    const int tid  = threadIdx.x;
    const int lane = tid & 31;
    const int g    = lane >> 2;
    const int tg   = lane & 3;
    const int wm   = (tid >> 5) & 3;
    const int wn   = tid >> 7;
    const int mbase = wm * 32;
    const int nbase = wn * 64;

    const int rowBase = blockIdx.y * 128;
    const int colBase = blockIdx.x * 128;

    float acc[2][8][4];
    #pragma unroll
    for (int mi = 0; mi < 2; mi++)
        #pragma unroll
        for (int ni = 0; ni < 8; ni++)
            #pragma unroll
            for (int r = 0; r < 4; r++) acc[mi][ni][r] = 0.0f;

    // ---- stage loader: A 128x32, B 128x32 (T) or 32x128 (N) ----
    auto loadStage = [&](int st, int kt) {
        float* Ad = AsAll + st * 128 * APITCH;
        #pragma unroll
        for (int r = 0; r < 4; r++) {
            int c   = r * 256 + tid;
            int row = c >> 3;                // 8 chunks per 32-float row
            int kq  = (c & 7) << 2;
            cp16((unsigned)__cvta_generic_to_shared(Ad + row * APITCH + kq),
                 A + (size_t)(rowBase + row) * lda + kt + kq);
        }
        float* Bd = BsAll + st * BSTG;
        if (TRANSB) {
            #pragma unroll
            for (int r = 0; r < 4; r++) {
                int c   = r * 256 + tid;
                int row = c >> 3;
                int kq  = (c & 7) << 2;
                cp16((unsigned)__cvta_generic_to_shared(Bd + row * APITCH + kq),
                     B + (size_t)(colBase + row) * ldb + kt + kq);
            }
        } else {
            #pragma unroll
            for (int r = 0; r < 4; r++) {
                int c    = r * 256 + tid;
                int krow = c >> 5;           // 32 chunks per 128-float row
                int nq   = (c & 31) << 2;
                cp16((unsigned)__cvta_generic_to_shared(Bd + krow * BPITCH + nq),
                     B + (size_t)(kt + krow) * ldb + colBase + nq);
            }
        }
    };

    const int nk = K >> 5;   // 32-k stages
    loadStage(0, 0);
    cp_commit();
    if (nk > 1) loadStage(1, BK);
    cp_commit();

    int st = 0;
    for (int it = 0; it < nk; it++) {
        cp_wait();
        __syncthreads();     // stage `st` complete+visible; all warps done reading
                             // the stage about to be overwritten below (WAR safe)

        int ktn = (it + NST - 1) << 5;
        int stn = st + NST - 1; if (stn >= NST) stn -= NST;
        if (ktn < K) loadStage(stn, ktn);
        cp_commit();

        const float* Asb = AsAll + st * 128 * APITCH;
        const float* Bsb = BsAll + st * BSTG;
        #pragma unroll
        for (int ks = 0; ks < BK; ks += 8) {
            unsigned a[2][4], b[8][2];
            #pragma unroll
            for (int mi = 0; mi < 2; mi++) {
                int m = mbase + mi * 16 + g;
                a[mi][0] = __float_as_uint(Asb[(size_t)m * APITCH + ks + tg]);
                a[mi][1] = __float_as_uint(Asb[(size_t)(m + 8) * APITCH + ks + tg]);
                a[mi][2] = __float_as_uint(Asb[(size_t)m * APITCH + ks + tg + 4]);
                a[mi][3] = __float_as_uint(Asb[(size_t)(m + 8) * APITCH + ks + tg + 4]);
            }
            #pragma unroll
            for (int ni = 0; ni < 8; ni++) {
                int n = nbase + ni * 8 + g;
                if (TRANSB) {
                    b[ni][0] = __float_as_uint(Bsb[(size_t)n * APITCH + ks + tg]);
                    b[ni][1] = __float_as_uint(Bsb[(size_t)n * APITCH + ks + tg + 4]);
                } else {
                    b[ni][0] = __float_as_uint(Bsb[(size_t)(ks + tg) * BPITCH + n]);
                    b[ni][1] = __float_as_uint(Bsb[(size_t)(ks + tg + 4) * BPITCH + n]);
                }
            }
            #pragma unroll
            for (int mi = 0; mi < 2; mi++)
                #pragma unroll
                for (int ni = 0; ni < 8; ni++)
                    mma_tf32(acc[mi][ni], a[mi], b[ni]);
        }

        st++; if (st >= NST) st = 0;
        // no trailing barrier: next iteration's top barrier provides WAR + visibility
    }

    // ---- Epilogue ----
    #pragma unroll
    for (int mi = 0; mi < 2; mi++) {
        #pragma unroll
        for (int ni = 0; ni < 8; ni++) {
            int row = rowBase + mbase + mi * 16 + g;
            int col = colBase + nbase + ni * 8 + tg * 2;
            float bx = 0.f, by = 0.f;
            if (BIAS) { bx = bias[col]; by = bias[col + 1]; }
            float2 v0, v1;
            v0.x = alpha * acc[mi][ni][0] + bx;
            v0.y = alpha * acc[mi][ni][1] + by;
            v1.x = alpha * acc[mi][ni][2] + bx;
            v1.y = alpha * acc[mi][ni][3] + by;
            if (RND) {
                v0.x = rndtf(v0.x); v0.y = rndtf(v0.y);
                v1.x = rndtf(v1.x); v1.y = rndtf(v1.y);
            }
            *(float2*)(C + (size_t)row * ldc + col)       = v0;
            *(float2*)(C + (size_t)(row + 8) * ldc + col) = v1;
        }
    }
}

// ---------------------------------------------------------------------------
// Cross-head mix + softmax, in-place over g_s. Elementwise mix in registers,
// 3 barriers, float4 I/O. One CTA per (b, n), 256 threads.
// ---------------------------------------------------------------------------
__global__ __launch_bounds__(256) void mix_softmax_kernel(
    float* __restrict__ S,
    const float* __restrict__ w_main,
    const float* __restrict__ w_rest)
{
    __shared__ float Mm[16];
    __shared__ float redA[4][8];
    __shared__ float redB[4][8];

    const int b    = blockIdx.x / NN;
    const int n    = blockIdx.x % NN;
    const int tid  = threadIdx.x;
    const int lane = tid & 31;
    const int wrp  = tid >> 5;

    if (tid < 16) {
        int i = tid >> 2, j = tid & 3;
        Mm[tid] = (i == j) ? w_main[i]
                           : w_rest[i * (HH - 1) + (j < i ? j : j - 1)];
    }
    __syncthreads();

    const size_t base = ((size_t)b * HH * NN + n) * NN + tid * 4;

    float4 sv[HH];
    #pragma unroll
    for (int h = 0; h < HH; h++)
        sv[h] = *(const float4*)(S + base + (size_t)h * NN * NN);

    float4 v[HH];
    float mx[HH];
    #pragma unroll
    for (int i = 0; i < HH; i++) {
        float m0 = Mm[i*4+0], m1 = Mm[i*4+1], m2 = Mm[i*4+2], m3 = Mm[i*4+3];
        v[i].x = m0*sv[0].x + m1*sv[1].x + m2*sv[2].x + m3*sv[3].x;
        v[i].y = m0*sv[0].y + m1*sv[1].y + m2*sv[2].y + m3*sv[3].y;
        v[i].z = m0*sv[0].z + m1*sv[1].z + m2*sv[2].z + m3*sv[3].z;
        v[i].w = m0*sv[0].w + m1*sv[1].w + m2*sv[2].w + m3*sv[3].w;
        mx[i] = fmaxf(fmaxf(v[i].x, v[i].y), fmaxf(v[i].z, v[i].w));
        #pragma unroll
        for (int o = 16; o > 0; o >>= 1)
            mx[i] = fmaxf(mx[i], __shfl_xor_sync(0xffffffffu, mx[i], o));
    }
    if (lane == 0) {
        #pragma unroll
        for (int i = 0; i < HH; i++) redA[i][wrp] = mx[i];
    }
    __syncthreads();

    float sm[HH];
    #pragma unroll
    for (int i = 0; i < HH; i++) {
        float rmax = redA[i][0];
        #pragma unroll
        for (int w = 1; w < 8; w++) rmax = fmaxf(rmax, redA[i][w]);
        v[i].x = expf(v[i].x - rmax);
        v[i].y = expf(v[i].y - rmax);
        v[i].z = expf(v[i].z - rmax);
        v[i].w = expf(v[i].w - rmax);
        sm[i] = (v[i].x + v[i].y) + (v[i].z + v[i].w);
        #pragma unroll
        for (int o = 16; o > 0; o >>= 1)
            sm[i] += __shfl_xor_sync(0xffffffffu, sm[i], o);
    }
    if (lane == 0) {
        #pragma unroll
        for (int i = 0; i < HH; i++) redB[i][wrp] = sm[i];
    }
    __syncthreads();

    #pragma unroll
    for (int i = 0; i < HH; i++) {
        float rsum = redB[i][0];
        #pragma unroll
        for (int w = 1; w < 8; w++) rsum += redB[i][w];
        float inv = 1.0f / rsum;
        float4 o;
        o.x = rndtf(v[i].x * inv);
        o.y = rndtf(v[i].y * inv);
        o.z = rndtf(v[i].z * inv);
        o.w = rndtf(v[i].w * inv);
        *(float4*)(S + base + (size_t)i * NN * NN) = o;
    }
}

// ---------------------------------------------------------------------------
extern "C" void kernel_launch(void* const* d_in, const int* in_sizes, int n_in,
                              void* d_out, int out_size)
{
    const float* x      = (const float*)d_in[0];  // [B,N,C]
    const float* w_qkv  = (const float*)d_in[1];  // [3C,C]
    const float* w_proj = (const float*)d_in[2];  // [C,C]
    const float* b_proj = (const float*)d_in[3];  // [C]
    const float* w_main = (const float*)d_in[4];  // [H]
    const float* w_rest = (const float*)d_in[5];  // [H,H-1]
    float* out = (float*)d_out;                   // [B,N,C]

    float* qkv; cudaGetSymbolAddress((void**)&qkv, g_qkv);
    float* S;   cudaGetSymbolAddress((void**)&S,   g_s);
    float* O;   cudaGetSymbolAddress((void**)&O,   g_o);
    float* xr;  cudaGetSymbolAddress((void**)&xr,  g_xr);
    float* wq;  cudaGetSymbolAddress((void**)&wq,  g_wqkvr);
    float* wp;  cudaGetSymbolAddress((void**)&wp,  g_wprojr);

    const int SMEM_T = NST * (128 * APITCH * 2) * 4;              // 110592 B
    const int SMEM_N = NST * (128 * APITCH + 32 * BPITCH) * 4;    // 107520 B
    cudaFuncSetAttribute(tgemm_kernel<true,  false, true >,
                         cudaFuncAttributeMaxDynamicSharedMemorySize, SMEM_T);
    cudaFuncSetAttribute(tgemm_kernel<true,  false, false>,
                         cudaFuncAttributeMaxDynamicSharedMemorySize, SMEM_T);
    cudaFuncSetAttribute(tgemm_kernel<false, false, true >,
                         cudaFuncAttributeMaxDynamicSharedMemorySize, SMEM_N);
    cudaFuncSetAttribute(tgemm_kernel<true,  true,  false>,
                         cudaFuncAttributeMaxDynamicSharedMemorySize, SMEM_T);

    // 0) tf32-round inputs into scratch
    round_kernel<<<(BN_TOK * CC / 4) / 256, 256>>>(x, xr, BN_TOK * CC / 4);
    round_kernel<<<(C3 * CC / 4) / 256, 256>>>(w_qkv, wq, C3 * CC / 4);
    round_kernel<<<(CC * CC / 4) / 256, 256>>>(w_proj, wp, CC * CC / 4);

    // 1) QKV = Xr @ Wqkv_r^T  (output tf32-rounded)
    tgemm_kernel<true, false, true><<<dim3(C3 / 128, BN_TOK / 128, 1), 256, SMEM_T>>>(
        xr, wq, qkv, nullptr,
        CC, CC, CC, C3,
        1, 0, 0, 0, 0, 0, 0, 1.0f);

    // 2) S[b,h] = scale * Q_bh @ K_bh^T : 32 x [1024,1024,128]
    tgemm_kernel<true, false, false><<<dim3(NN / 128, NN / 128, BB * HH), 256, SMEM_T>>>(
        qkv, qkv + CC, S, nullptr,
        HD, C3, C3, NN,
        HH,
        /*sAi*/ HD, /*sAo*/ (long long)NN * C3,
        /*sBi*/ HD, /*sBo*/ (long long)NN * C3,
        /*sCi*/ (long long)NN * NN, /*sCo*/ (long long)HH * NN * NN,
        SCALE);

    // 3) cross-head mix + softmax (in-place, P tf32-rounded)
    mix_softmax_kernel<<<BB * NN, 256>>>(S, w_main, w_rest);

    // 4) O[b,h] = P_bh @ V_bh : 32 x [1024,128,1024] (output tf32-rounded)
    tgemm_kernel<false, false, true><<<dim3(HD / 128, NN / 128, BB * HH), 256, SMEM_N>>>(
        S, qkv + 2 * CC, O, nullptr,
        NN, NN, C3, CC,
        HH,
        /*sAi*/ (long long)NN * NN, /*sAo*/ (long long)HH * NN * NN,
        /*sBi*/ HD, /*sBo*/ (long long)NN * C3,
        /*sCi*/ HD, /*sCo*/ (long long)NN * CC,
        1.0f);

    // 5) out = O @ Wproj_r^T + b : [8192,512,512] (full fp32 output)
    tgemm_kernel<true, true, false><<<dim3(CC / 128, BN_TOK / 128, 1), 256, SMEM_T>>>(
        O, wp, out, b_proj,
        CC, CC, CC, CC,
        1, 0, 0, 0, 0, 0, 0, 1.0f);
}